// round 2
// baseline (speedup 1.0000x reference)
#include <cuda_runtime.h>
#include <cstdint>

#define N_NODES 100000
#define E_EDGES 3200000
#define D 256

// ---------------- scratch (device globals: no allocation allowed) ----------
__device__ int   g_cnt[N_NODES];
__device__ float g_rdeg[N_NODES];
__device__ float g_A[(size_t)N_NODES * D];   // 102.4 MB aggregation buffer
__device__ int   g_is64;

// ---------------- dtype detection ------------------------------------------
// If edge_index is int64 (little-endian), every odd int32 word in the first
// 2E int32 span is a high word of a value < 2^31 -> exactly 0.
// If int32, odd words are random src values in [0,1e5): P(all 4096 zero) ~ 0.
__global__ void detect_kernel(const unsigned int* __restrict__ p) {
    __shared__ int any;
    if (threadIdx.x == 0) any = 0;
    __syncthreads();
    for (int k = threadIdx.x; k < 4096; k += blockDim.x) {
        size_t idx = 1 + 2ull * (size_t)k * 781ull;   // odd, < 6.4M
        if (p[idx] != 0u) atomicOr(&any, 1);
    }
    __syncthreads();
    if (threadIdx.x == 0) g_is64 = any ? 0 : 1;
}

// ---------------- degree ----------------------------------------------------
__global__ void zero_cnt_kernel() {
    int i = blockIdx.x * blockDim.x + threadIdx.x;
    if (i < N_NODES) g_cnt[i] = 0;
}

__global__ void count_kernel(const void* __restrict__ ei) {
    const int is64 = g_is64;
    int stride = gridDim.x * blockDim.x;
    for (int e = blockIdx.x * blockDim.x + threadIdx.x; e < E_EDGES; e += stride) {
        int s = is64 ? (int)((const long long*)ei)[e] : ((const int*)ei)[e];
        atomicAdd(&g_cnt[s], 1);
    }
}

__global__ void rdeg_kernel() {
    int i = blockIdx.x * blockDim.x + threadIdx.x;
    if (i < N_NODES) g_rdeg[i] = 1.0f / (float)(g_cnt[i] + 1);
}

// ---------------- A init: self-loop term A[i] = X[i] * rdeg[i] --------------
__global__ void init_kernel(const float* __restrict__ X) {
    const int total = N_NODES * (D / 4);   // float4 count
    int stride = gridDim.x * blockDim.x;
    for (int i = blockIdx.x * blockDim.x + threadIdx.x; i < total; i += stride) {
        int row = i >> 6;                  // / (D/4)
        float4 v = ((const float4*)X)[i];
        float r = g_rdeg[row];
        v.x *= r; v.y *= r; v.z *= r; v.w *= r;
        ((float4*)g_A)[i] = v;
    }
}

// ---------------- edge scatter: A[src] += X[dst] * rdeg[dst] ----------------
__device__ __forceinline__ void red_add_v4(float4* addr, float4 v) {
    asm volatile("red.global.add.v4.f32 [%0], {%1, %2, %3, %4};"
                 :: "l"(addr), "f"(v.x), "f"(v.y), "f"(v.z), "f"(v.w)
                 : "memory");
}

__global__ void edge_kernel(const void* __restrict__ ei, const float* __restrict__ X) {
    const int is64 = g_is64;
    const int lane  = threadIdx.x & 31;
    int warp   = blockIdx.x * (blockDim.x >> 5) + (threadIdx.x >> 5);
    int nwarps = gridDim.x * (blockDim.x >> 5);
    for (int e = warp; e < E_EDGES; e += nwarps) {
        long long s, d;
        if (is64) {
            s = ((const long long*)ei)[e];
            d = ((const long long*)ei)[E_EDGES + e];
        } else {
            s = ((const int*)ei)[e];
            d = ((const int*)ei)[E_EDGES + e];
        }
        float r = g_rdeg[d];
        const float4* xr = (const float4*)(X + (size_t)d * D);
        float4*       ar = (float4*)(g_A + (size_t)s * D);
        #pragma unroll
        for (int i = 0; i < 2; i++) {
            float4 v = xr[lane + 32 * i];
            v.x *= r; v.y *= r; v.z *= r; v.w *= r;
            red_add_v4(&ar[lane + 32 * i], v);
        }
    }
}

// ---------------- GEMM: out = A @ W  (fp32 SIMT, 128x128x16 tiles) ----------
#define BM 128
#define BN 128
#define BK 16

__global__ __launch_bounds__(256) void gemm_kernel(const float* __restrict__ W,
                                                   float* __restrict__ out) {
    __shared__ float As[BK][BM];
    __shared__ float Bs[BK][BN];

    const int bx = blockIdx.x;           // N tile (0..1)
    const int by = blockIdx.y;           // M tile (0..781)
    const int tid = threadIdx.x;
    const int tx = tid & 15;             // 16 col groups of 8
    const int ty = tid >> 4;             // 16 row groups of 8
    const int rowBase = by * BM;
    const int colBase = bx * BN;

    // A tile load mapping: 128x16 floats, 2 x float4 per thread
    const int aRow = tid >> 2;           // 0..63
    const int aCol = (tid & 3) * 4;      // 0,4,8,12
    // B tile load mapping: 16x128 floats, 2 x float4 per thread
    const int bRow = tid >> 5;           // 0..7
    const int bCol = (tid & 31) * 4;     // 0..124

    float acc[8][8] = {};

    for (int k0 = 0; k0 < D; k0 += BK) {
        #pragma unroll
        for (int i = 0; i < 2; i++) {
            int r = rowBase + aRow + i * 64;
            float4 v = make_float4(0.f, 0.f, 0.f, 0.f);
            if (r < N_NODES)
                v = *(const float4*)(g_A + (size_t)r * D + k0 + aCol);
            As[aCol + 0][aRow + i * 64] = v.x;
            As[aCol + 1][aRow + i * 64] = v.y;
            As[aCol + 2][aRow + i * 64] = v.z;
            As[aCol + 3][aRow + i * 64] = v.w;
        }
        #pragma unroll
        for (int i = 0; i < 2; i++) {
            int r = bRow + i * 8;
            *(float4*)&Bs[r][bCol] =
                *(const float4*)(W + (size_t)(k0 + r) * D + colBase + bCol);
        }
        __syncthreads();

        #pragma unroll
        for (int k = 0; k < BK; k++) {
            float a[8], b[8];
            #pragma unroll
            for (int i = 0; i < 8; i++) a[i] = As[k][ty * 8 + i];
            #pragma unroll
            for (int j = 0; j < 8; j++) b[j] = Bs[k][tx * 8 + j];
            #pragma unroll
            for (int i = 0; i < 8; i++)
                #pragma unroll
                for (int j = 0; j < 8; j++)
                    acc[i][j] += a[i] * b[j];
        }
        __syncthreads();
    }

    #pragma unroll
    for (int i = 0; i < 8; i++) {
        int r = rowBase + ty * 8 + i;
        if (r < N_NODES) {
            #pragma unroll
            for (int j = 0; j < 8; j += 4) {
                float4 v = make_float4(acc[i][j], acc[i][j + 1],
                                       acc[i][j + 2], acc[i][j + 3]);
                *(float4*)(out + (size_t)r * D + colBase + tx * 8 + j) = v;
            }
        }
    }
}

// ---------------- launch ----------------------------------------------------
extern "C" void kernel_launch(void* const* d_in, const int* in_sizes, int n_in,
                              void* d_out, int out_size) {
    const float* X  = (const float*)d_in[0];
    const void*  EI = d_in[1];
    const float* W  = (const float*)d_in[2];
    float*       out = (float*)d_out;

    detect_kernel<<<1, 256>>>((const unsigned int*)EI);
    zero_cnt_kernel<<<(N_NODES + 255) / 256, 256>>>();
    count_kernel<<<4096, 256>>>(EI);
    rdeg_kernel<<<(N_NODES + 255) / 256, 256>>>();
    init_kernel<<<8192, 256>>>(X);
    edge_kernel<<<16384, 256>>>(EI, X);
    gemm_kernel<<<dim3(2, 782), 256>>>(W, out);
}

// round 6
// speedup vs baseline: 1.0464x; 1.0464x over previous
#include <cuda_runtime.h>
#include <cstdint>

#define N_NODES 100000
#define E_EDGES 3200000
#define D 256
#define M_TILES 782            // ceil(100000/128)
#define M_PAD (M_TILES * 128)  // 100096 rows (padded; tail rows stay zero)

// ---------------- scratch (device globals: no allocation allowed) ----------
__device__ int   g_cnt[N_NODES];
__device__ float g_rdeg[N_NODES];
__device__ float g_A[(size_t)M_PAD * D];   // 102.5 MB aggregation buffer
__device__ float g_Whi[D * D];             // W tf32-hi  [k][n] row-major
__device__ float g_Wlo[D * D];             // W tf32-lo residual
__device__ int   g_is64;

// ---------------- dtype detection ------------------------------------------
// int64 edge values < 2^31 -> every odd 32-bit word is 0. int32 -> random.
__global__ void detect_kernel(const unsigned int* __restrict__ p) {
    __shared__ int any;
    if (threadIdx.x == 0) any = 0;
    __syncthreads();
    for (int k = threadIdx.x; k < 4096; k += blockDim.x) {
        size_t idx = 1 + 2ull * (size_t)k * 781ull;
        if (p[idx] != 0u) atomicOr(&any, 1);
    }
    __syncthreads();
    if (threadIdx.x == 0) g_is64 = any ? 0 : 1;
}

// ---------------- degree ----------------------------------------------------
__global__ void zero_cnt_kernel() {
    int i = blockIdx.x * blockDim.x + threadIdx.x;
    if (i < N_NODES) g_cnt[i] = 0;
}

__global__ void count_kernel(const void* __restrict__ ei) {
    const int is64 = g_is64;
    int stride = gridDim.x * blockDim.x;
    for (int e = blockIdx.x * blockDim.x + threadIdx.x; e < E_EDGES; e += stride) {
        int s = is64 ? (int)((const long long*)ei)[e] : ((const int*)ei)[e];
        atomicAdd(&g_cnt[s], 1);
    }
}

__global__ void rdeg_kernel() {
    int i = blockIdx.x * blockDim.x + threadIdx.x;
    if (i < N_NODES) g_rdeg[i] = 1.0f / (float)(g_cnt[i] + 1);
}

// ---------------- A init: self-loop term A[i] = X[i] * rdeg[i] --------------
__global__ void init_kernel(const float* __restrict__ X) {
    const int total = N_NODES * (D / 4);
    int stride = gridDim.x * blockDim.x;
    for (int i = blockIdx.x * blockDim.x + threadIdx.x; i < total; i += stride) {
        int row = i >> 6;
        float4 v = ((const float4*)X)[i];
        float r = g_rdeg[row];
        v.x *= r; v.y *= r; v.z *= r; v.w *= r;
        ((float4*)g_A)[i] = v;
    }
}

// ---------------- edge scatter: A[src] += X[dst] * rdeg[dst] ----------------
__device__ __forceinline__ void red_add_v4(float4* addr, float4 v) {
    asm volatile("red.global.add.v4.f32 [%0], {%1, %2, %3, %4};"
                 :: "l"(addr), "f"(v.x), "f"(v.y), "f"(v.z), "f"(v.w)
                 : "memory");
}

__global__ void edge_kernel(const void* __restrict__ ei, const float* __restrict__ X) {
    const int is64 = g_is64;
    const int lane  = threadIdx.x & 31;
    int warp   = blockIdx.x * (blockDim.x >> 5) + (threadIdx.x >> 5);
    int nwarps = gridDim.x * (blockDim.x >> 5);
    for (int e = warp; e < E_EDGES; e += nwarps) {
        long long s, d;
        if (is64) {
            s = ((const long long*)ei)[e];
            d = ((const long long*)ei)[E_EDGES + e];
        } else {
            s = ((const int*)ei)[e];
            d = ((const int*)ei)[E_EDGES + e];
        }
        float r = g_rdeg[d];
        const float4* xr = (const float4*)(X + (size_t)d * D);
        float4*       ar = (float4*)(g_A + (size_t)s * D);
        #pragma unroll
        for (int i = 0; i < 2; i++) {
            float4 v = xr[lane + 32 * i];
            v.x *= r; v.y *= r; v.z *= r; v.w *= r;
            red_add_v4(&ar[lane + 32 * i], v);
        }
    }
}

// ---------------- W prep: tf32 hi/lo split (no transpose needed) ------------
__global__ void wprep_kernel(const float* __restrict__ W) {
    int idx = blockIdx.x * blockDim.x + threadIdx.x;   // 0..65535
    float w  = W[idx];
    float hi = __uint_as_float(__float_as_uint(w) & 0xFFFFE000u);
    g_Whi[idx] = hi;
    g_Wlo[idx] = w - hi;
}

// ---------------- GEMM: out = A @ W via mma.sync tf32 (3xTF32) --------------
// CTA: 128(M) x 128(N), 8 warps as 4x2, warp tile 32x64, BK=32, 8 K-chunks.
#define PITCH_A 36     // floats; (4g+tg)%32 all-distinct -> conflict-free LDS
#define PITCH_B 136
#define SM_AH 0
#define SM_AL (128 * PITCH_A)
#define SM_BH (2 * 128 * PITCH_A)
#define SM_BL (SM_BH + 32 * PITCH_B)
#define SMEM_FLOATS (SM_BL + 32 * PITCH_B)   // 17920 floats = 71680 B

__device__ __forceinline__ void mma_tf32(float* c, const float* a, float b0, float b1) {
    asm volatile(
        "mma.sync.aligned.m16n8k8.row.col.f32.tf32.tf32.f32 "
        "{%0,%1,%2,%3}, {%4,%5,%6,%7}, {%8,%9}, {%0,%1,%2,%3};"
        : "+f"(c[0]), "+f"(c[1]), "+f"(c[2]), "+f"(c[3])
        : "r"(__float_as_uint(a[0])), "r"(__float_as_uint(a[1])),
          "r"(__float_as_uint(a[2])), "r"(__float_as_uint(a[3])),
          "r"(__float_as_uint(b0)), "r"(__float_as_uint(b1)));
}

__global__ __launch_bounds__(256) void gemm_mma_kernel(float* __restrict__ out) {
    extern __shared__ float smem[];
    float* AH = smem + SM_AH;
    float* AL = smem + SM_AL;
    float* BH = smem + SM_BH;
    float* BL = smem + SM_BL;

    const int tid  = threadIdx.x;
    const int wid  = tid >> 5;
    const int lane = tid & 31;
    const int g    = lane >> 2;      // group id 0..7
    const int tg   = lane & 3;       // thread-in-group 0..3
    const int wm   = wid >> 1;       // warp m 0..3
    const int wn   = wid & 1;        // warp n 0..1

    const size_t rowBase = (size_t)blockIdx.y * 128;
    const int    colBase = blockIdx.x * 128;
    const float* Atile = g_A + rowBase * D;

    float acc[2][8][4];
    #pragma unroll
    for (int i = 0; i < 2; i++)
        #pragma unroll
        for (int j = 0; j < 8; j++)
            #pragma unroll
            for (int k = 0; k < 4; k++) acc[i][j][k] = 0.f;

    #pragma unroll 1
    for (int c = 0; c < 8; c++) {
        const int k0 = c * 32;
        // --- A chunk 128x32 -> hi/lo SMEM (4 float4 per thread) ---
        #pragma unroll
        for (int i = 0; i < 4; i++) {
            int idx = tid + i * 256;             // 0..1023
            int r   = idx >> 3;
            int c4  = (idx & 7) * 4;
            float4 v = *(const float4*)(Atile + (size_t)r * D + k0 + c4);
            uint4 u = *(uint4*)&v;
            float4 hi;
            hi.x = __uint_as_float(u.x & 0xFFFFE000u);
            hi.y = __uint_as_float(u.y & 0xFFFFE000u);
            hi.z = __uint_as_float(u.z & 0xFFFFE000u);
            hi.w = __uint_as_float(u.w & 0xFFFFE000u);
            float4 lo = make_float4(v.x - hi.x, v.y - hi.y, v.z - hi.z, v.w - hi.w);
            *(float4*)(AH + r * PITCH_A + c4) = hi;
            *(float4*)(AL + r * PITCH_A + c4) = lo;
        }
        // --- B chunk 32x128 from pre-split W (4 float4 per thread each) ---
        #pragma unroll
        for (int i = 0; i < 4; i++) {
            int idx = tid + i * 256;             // 0..1023
            int kk  = idx >> 5;
            int c4  = (idx & 31) * 4;
            *(float4*)(BH + kk * PITCH_B + c4) =
                *(const float4*)(g_Whi + (size_t)(k0 + kk) * D + colBase + c4);
            *(float4*)(BL + kk * PITCH_B + c4) =
                *(const float4*)(g_Wlo + (size_t)(k0 + kk) * D + colBase + c4);
        }
        __syncthreads();

        #pragma unroll
        for (int ks = 0; ks < 4; ks++) {
            const int k = ks * 8;
            float ah[2][4], al[2][4];
            #pragma unroll
            for (int mt = 0; mt < 2; mt++) {
                int row = wm * 32 + mt * 16;
                ah[mt][0] = AH[(row + g) * PITCH_A + k + tg];
                ah[mt][1] = AH[(row + g + 8) * PITCH_A + k + tg];
                ah[mt][2] = AH[(row + g) * PITCH_A + k + tg + 4];
                ah[mt][3] = AH[(row + g + 8) * PITCH_A + k + tg + 4];
                al[mt][0] = AL[(row + g) * PITCH_A + k + tg];
                al[mt][1] = AL[(row + g + 8) * PITCH_A + k + tg];
                al[mt][2] = AL[(row + g) * PITCH_A + k + tg + 4];
                al[mt][3] = AL[(row + g + 8) * PITCH_A + k + tg + 4];
            }
            #pragma unroll
            for (int nt = 0; nt < 8; nt++) {
                int n = wn * 64 + nt * 8;
                float bh0 = BH[(k + tg) * PITCH_B + n + g];
                float bh1 = BH[(k + tg + 4) * PITCH_B + n + g];
                float bl0 = BL[(k + tg) * PITCH_B + n + g];
                float bl1 = BL[(k + tg + 4) * PITCH_B + n + g];
                #pragma unroll
                for (int mt = 0; mt < 2; mt++) {
                    mma_tf32(acc[mt][nt], ah[mt], bh0, bh1);
                    mma_tf32(acc[mt][nt], ah[mt], bl0, bl1);
                    mma_tf32(acc[mt][nt], al[mt], bh0, bh1);
                }
            }
        }
        __syncthreads();
    }

    // --- epilogue: c0,c1 -> (row, n+tg*2), c2,c3 -> (row+8, n+tg*2) ---
    #pragma unroll
    for (int mt = 0; mt < 2; mt++) {
        size_t r0 = rowBase + wm * 32 + mt * 16 + g;
        #pragma unroll
        for (int nt = 0; nt < 8; nt++) {
            int col = colBase + wn * 64 + nt * 8 + tg * 2;
            if (r0 < N_NODES)
                *(float2*)(out + r0 * D + col) = make_float2(acc[mt][nt][0], acc[mt][nt][1]);
            if (r0 + 8 < N_NODES)
                *(float2*)(out + (r0 + 8) * D + col) = make_float2(acc[mt][nt][2], acc[mt][nt][3]);
        }
    }
}

// ---------------- launch ----------------------------------------------------
extern "C" void kernel_launch(void* const* d_in, const int* in_sizes, int n_in,
                              void* d_out, int out_size) {
    const float* X  = (const float*)d_in[0];
    const void*  EI = d_in[1];
    const float* W  = (const float*)d_in[2];
    float*       out = (float*)d_out;

    cudaFuncSetAttribute(gemm_mma_kernel,
                         cudaFuncAttributeMaxDynamicSharedMemorySize,
                         SMEM_FLOATS * 4);

    detect_kernel<<<1, 256>>>((const unsigned int*)EI);
    zero_cnt_kernel<<<(N_NODES + 255) / 256, 256>>>();
    count_kernel<<<4096, 256>>>(EI);
    rdeg_kernel<<<(N_NODES + 255) / 256, 256>>>();
    init_kernel<<<8192, 256>>>(X);
    edge_kernel<<<16384, 256>>>(EI, X);
    wprep_kernel<<<256, 256>>>(W);
    gemm_mma_kernel<<<dim3(2, M_TILES), 256, SMEM_FLOATS * 4>>>(out);
}

// round 9
// speedup vs baseline: 2.1427x; 2.0476x over previous
#include <cuda_runtime.h>
#include <cstdint>

#define N_NODES 100000
#define E_EDGES 3200000
#define D 256
#define M_TILES 782            // ceil(100000/128)
#define M_PAD (M_TILES * 128)  // 100096 rows (padded; tail rows stay zero)

// ---------------- scratch (device globals: no allocation allowed) ----------
__device__ int   g_cnt[N_NODES];
__device__ float g_rdeg[N_NODES];
__device__ int   g_rowptr[N_NODES];
__device__ int   g_pos[N_NODES];
__device__ int   g_bsum[128];
__device__ int   g_bsumx[128];
__device__ int   g_adj[E_EDGES];           // dst packed by src (int32)
__device__ float g_A[(size_t)M_PAD * D];   // 102.5 MB aggregation buffer
__device__ float g_Whi[D * D];             // W tf32-hi  [k][n] row-major
__device__ float g_Wlo[D * D];             // W tf32-lo residual
__device__ int   g_is64;

// ---------------- dtype detection ------------------------------------------
// int64 edge values < 2^31 -> every odd 32-bit word is 0. int32 -> random.
__global__ void detect_kernel(const unsigned int* __restrict__ p) {
    __shared__ int any;
    if (threadIdx.x == 0) any = 0;
    __syncthreads();
    for (int k = threadIdx.x; k < 4096; k += blockDim.x) {
        size_t idx = 1 + 2ull * (size_t)k * 781ull;
        if (p[idx] != 0u) atomicOr(&any, 1);
    }
    __syncthreads();
    if (threadIdx.x == 0) g_is64 = any ? 0 : 1;
}

// ---------------- degree ----------------------------------------------------
__global__ void zero_cnt_kernel() {
    int i = blockIdx.x * blockDim.x + threadIdx.x;
    if (i < N_NODES) g_cnt[i] = 0;
}

__global__ void count_kernel(const void* __restrict__ ei) {
    const int is64 = g_is64;
    int stride = gridDim.x * blockDim.x;
    for (int e = blockIdx.x * blockDim.x + threadIdx.x; e < E_EDGES; e += stride) {
        int s = is64 ? (int)((const long long*)ei)[e] : ((const int*)ei)[e];
        atomicAdd(&g_cnt[s], 1);
    }
}

__global__ void rdeg_kernel() {
    int i = blockIdx.x * blockDim.x + threadIdx.x;
    if (i < N_NODES) g_rdeg[i] = 1.0f / (float)(g_cnt[i] + 1);
}

// ---------------- prefix scan of g_cnt -> g_rowptr (exclusive) -------------
// scan1: 1024 elems per block (256 thr x 4), exclusive-within-block
__global__ void scan1_kernel() {
    __shared__ int ssum[256];
    int b = blockIdx.x, t = threadIdx.x;
    int base = b * 1024 + t * 4;
    int v[4];
    #pragma unroll
    for (int k = 0; k < 4; k++)
        v[k] = (base + k < N_NODES) ? g_cnt[base + k] : 0;
    int s = v[0] + v[1] + v[2] + v[3];
    ssum[t] = s;
    __syncthreads();
    #pragma unroll
    for (int off = 1; off < 256; off <<= 1) {
        int x = (t >= off) ? ssum[t - off] : 0;
        __syncthreads();
        ssum[t] += x;
        __syncthreads();
    }
    if (t == 255) g_bsum[b] = ssum[255];
    int run = ssum[t] - s;   // exclusive within block
    #pragma unroll
    for (int k = 0; k < 4; k++) {
        if (base + k < N_NODES) g_rowptr[base + k] = run;
        run += v[k];
    }
}

// scan2: single block scans the 98 block sums (exclusive)
__global__ void scan2_kernel() {
    __shared__ int sb[128];
    int t = threadIdx.x;
    int nb = (N_NODES + 1023) / 1024;  // 98
    int orig = (t < nb) ? g_bsum[t] : 0;
    sb[t] = orig;
    __syncthreads();
    #pragma unroll
    for (int off = 1; off < 128; off <<= 1) {
        int x = (t >= off) ? sb[t - off] : 0;
        __syncthreads();
        sb[t] += x;
        __syncthreads();
    }
    g_bsumx[t] = sb[t] - orig;
}

// scan3: add block offsets; init atomic cursors
__global__ void scan3_kernel() {
    int i = blockIdx.x * blockDim.x + threadIdx.x;
    if (i < N_NODES) {
        int rp = g_rowptr[i] + g_bsumx[i >> 10];
        g_rowptr[i] = rp;
        g_pos[i] = rp;
    }
}

// ---------------- scatter edges into CSR (dst as int32) ---------------------
__global__ void scatter_kernel(const void* __restrict__ ei) {
    const int is64 = g_is64;
    int stride = gridDim.x * blockDim.x;
    for (int e = blockIdx.x * blockDim.x + threadIdx.x; e < E_EDGES; e += stride) {
        int s, d;
        if (is64) {
            s = (int)((const long long*)ei)[e];
            d = (int)((const long long*)ei)[E_EDGES + e];
        } else {
            s = ((const int*)ei)[e];
            d = ((const int*)ei)[E_EDGES + e];
        }
        int p = atomicAdd(&g_pos[s], 1);
        g_adj[p] = d;
    }
}

// ---------------- aggregation: one warp per node, register accumulators -----
// A[i] = X[i]*rdeg[i] + sum_{j in adj(i)} X[j]*rdeg[j]
__global__ __launch_bounds__(256) void agg_kernel(const float* __restrict__ X) {
    int w = blockIdx.x * 8 + (threadIdx.x >> 5);
    if (w >= N_NODES) return;
    const int lane = threadIdx.x & 31;
    const float4* X4 = (const float4*)X;

    float r = g_rdeg[w];
    float4 a0 = X4[(size_t)w * 64 + lane];
    float4 a1 = X4[(size_t)w * 64 + 32 + lane];
    a0.x *= r; a0.y *= r; a0.z *= r; a0.w *= r;
    a1.x *= r; a1.y *= r; a1.z *= r; a1.w *= r;

    const int start = g_rowptr[w];
    const int end   = start + g_cnt[w];
    for (int j = start; j < end; j++) {
        int d = g_adj[j];                       // warp-uniform broadcast load
        float rd = g_rdeg[d];
        const float4* xr = X4 + (size_t)d * 64;
        float4 v0 = xr[lane];
        float4 v1 = xr[lane + 32];
        a0.x += v0.x * rd; a0.y += v0.y * rd; a0.z += v0.z * rd; a0.w += v0.w * rd;
        a1.x += v1.x * rd; a1.y += v1.y * rd; a1.z += v1.z * rd; a1.w += v1.w * rd;
    }
    float4* ar = (float4*)(g_A + (size_t)w * D);
    ar[lane]      = a0;
    ar[lane + 32] = a1;
}

// ---------------- W prep: tf32 hi/lo split (no transpose needed) ------------
__global__ void wprep_kernel(const float* __restrict__ W) {
    int idx = blockIdx.x * blockDim.x + threadIdx.x;   // 0..65535
    float w  = W[idx];
    float hi = __uint_as_float(__float_as_uint(w) & 0xFFFFE000u);
    g_Whi[idx] = hi;
    g_Wlo[idx] = w - hi;
}

// ---------------- GEMM: out = A @ W via mma.sync tf32 (3xTF32) --------------
// CTA: 128(M) x 128(N), 8 warps as 4x2, warp tile 32x64, BK=32, 8 K-chunks.
#define PITCH_A 36     // floats; (4g+tg)%32 all-distinct -> conflict-free LDS
#define PITCH_B 136
#define SM_AH 0
#define SM_AL (128 * PITCH_A)
#define SM_BH (2 * 128 * PITCH_A)
#define SM_BL (SM_BH + 32 * PITCH_B)
#define SMEM_FLOATS (SM_BL + 32 * PITCH_B)   // 17920 floats = 71680 B

__device__ __forceinline__ void mma_tf32(float* c, const float* a, float b0, float b1) {
    asm volatile(
        "mma.sync.aligned.m16n8k8.row.col.f32.tf32.tf32.f32 "
        "{%0,%1,%2,%3}, {%4,%5,%6,%7}, {%8,%9}, {%0,%1,%2,%3};"
        : "+f"(c[0]), "+f"(c[1]), "+f"(c[2]), "+f"(c[3])
        : "r"(__float_as_uint(a[0])), "r"(__float_as_uint(a[1])),
          "r"(__float_as_uint(a[2])), "r"(__float_as_uint(a[3])),
          "r"(__float_as_uint(b0)), "r"(__float_as_uint(b1)));
}

__global__ __launch_bounds__(256) void gemm_mma_kernel(float* __restrict__ out) {
    extern __shared__ float smem[];
    float* AH = smem + SM_AH;
    float* AL = smem + SM_AL;
    float* BH = smem + SM_BH;
    float* BL = smem + SM_BL;

    const int tid  = threadIdx.x;
    const int wid  = tid >> 5;
    const int lane = tid & 31;
    const int g    = lane >> 2;      // group id 0..7
    const int tg   = lane & 3;       // thread-in-group 0..3
    const int wm   = wid >> 1;       // warp m 0..3
    const int wn   = wid & 1;        // warp n 0..1

    const size_t rowBase = (size_t)blockIdx.y * 128;
    const int    colBase = blockIdx.x * 128;
    const float* Atile = g_A + rowBase * D;

    float acc[2][8][4];
    #pragma unroll
    for (int i = 0; i < 2; i++)
        #pragma unroll
        for (int j = 0; j < 8; j++)
            #pragma unroll
            for (int k = 0; k < 4; k++) acc[i][j][k] = 0.f;

    #pragma unroll 1
    for (int c = 0; c < 8; c++) {
        const int k0 = c * 32;
        // --- A chunk 128x32 -> hi/lo SMEM (4 float4 per thread) ---
        #pragma unroll
        for (int i = 0; i < 4; i++) {
            int idx = tid + i * 256;             // 0..1023
            int r   = idx >> 3;
            int c4  = (idx & 7) * 4;
            float4 v = *(const float4*)(Atile + (size_t)r * D + k0 + c4);
            uint4 u = *(uint4*)&v;
            float4 hi;
            hi.x = __uint_as_float(u.x & 0xFFFFE000u);
            hi.y = __uint_as_float(u.y & 0xFFFFE000u);
            hi.z = __uint_as_float(u.z & 0xFFFFE000u);
            hi.w = __uint_as_float(u.w & 0xFFFFE000u);
            float4 lo = make_float4(v.x - hi.x, v.y - hi.y, v.z - hi.z, v.w - hi.w);
            *(float4*)(AH + r * PITCH_A + c4) = hi;
            *(float4*)(AL + r * PITCH_A + c4) = lo;
        }
        // --- B chunk 32x128 from pre-split W (4 float4 per thread each) ---
        #pragma unroll
        for (int i = 0; i < 4; i++) {
            int idx = tid + i * 256;             // 0..1023
            int kk  = idx >> 5;
            int c4  = (idx & 31) * 4;
            *(float4*)(BH + kk * PITCH_B + c4) =
                *(const float4*)(g_Whi + (size_t)(k0 + kk) * D + colBase + c4);
            *(float4*)(BL + kk * PITCH_B + c4) =
                *(const float4*)(g_Wlo + (size_t)(k0 + kk) * D + colBase + c4);
        }
        __syncthreads();

        #pragma unroll
        for (int ks = 0; ks < 4; ks++) {
            const int k = ks * 8;
            float ah[2][4], al[2][4];
            #pragma unroll
            for (int mt = 0; mt < 2; mt++) {
                int row = wm * 32 + mt * 16;
                ah[mt][0] = AH[(row + g) * PITCH_A + k + tg];
                ah[mt][1] = AH[(row + g + 8) * PITCH_A + k + tg];
                ah[mt][2] = AH[(row + g) * PITCH_A + k + tg + 4];
                ah[mt][3] = AH[(row + g + 8) * PITCH_A + k + tg + 4];
                al[mt][0] = AL[(row + g) * PITCH_A + k + tg];
                al[mt][1] = AL[(row + g + 8) * PITCH_A + k + tg];
                al[mt][2] = AL[(row + g) * PITCH_A + k + tg + 4];
                al[mt][3] = AL[(row + g + 8) * PITCH_A + k + tg + 4];
            }
            #pragma unroll
            for (int nt = 0; nt < 8; nt++) {
                int n = wn * 64 + nt * 8;
                float bh0 = BH[(k + tg) * PITCH_B + n + g];
                float bh1 = BH[(k + tg + 4) * PITCH_B + n + g];
                float bl0 = BL[(k + tg) * PITCH_B + n + g];
                float bl1 = BL[(k + tg + 4) * PITCH_B + n + g];
                #pragma unroll
                for (int mt = 0; mt < 2; mt++) {
                    mma_tf32(acc[mt][nt], ah[mt], bh0, bh1);
                    mma_tf32(acc[mt][nt], ah[mt], bl0, bl1);
                    mma_tf32(acc[mt][nt], al[mt], bh0, bh1);
                }
            }
        }
        __syncthreads();
    }

    // --- epilogue: c0,c1 -> (row, n+tg*2), c2,c3 -> (row+8, n+tg*2) ---
    #pragma unroll
    for (int mt = 0; mt < 2; mt++) {
        size_t r0 = rowBase + wm * 32 + mt * 16 + g;
        #pragma unroll
        for (int nt = 0; nt < 8; nt++) {
            int col = colBase + wn * 64 + nt * 8 + tg * 2;
            if (r0 < N_NODES)
                *(float2*)(out + r0 * D + col) = make_float2(acc[mt][nt][0], acc[mt][nt][1]);
            if (r0 + 8 < N_NODES)
                *(float2*)(out + (r0 + 8) * D + col) = make_float2(acc[mt][nt][2], acc[mt][nt][3]);
        }
    }
}

// ---------------- launch ----------------------------------------------------
extern "C" void kernel_launch(void* const* d_in, const int* in_sizes, int n_in,
                              void* d_out, int out_size) {
    const float* X  = (const float*)d_in[0];
    const void*  EI = d_in[1];
    const float* W  = (const float*)d_in[2];
    float*       out = (float*)d_out;

    cudaFuncSetAttribute(gemm_mma_kernel,
                         cudaFuncAttributeMaxDynamicSharedMemorySize,
                         SMEM_FLOATS * 4);

    detect_kernel<<<1, 256>>>((const unsigned int*)EI);
    zero_cnt_kernel<<<(N_NODES + 255) / 256, 256>>>();
    count_kernel<<<4096, 256>>>(EI);
    rdeg_kernel<<<(N_NODES + 255) / 256, 256>>>();
    scan1_kernel<<<(N_NODES + 1023) / 1024, 256>>>();
    scan2_kernel<<<1, 128>>>();
    scan3_kernel<<<(N_NODES + 255) / 256, 256>>>();
    scatter_kernel<<<4096, 256>>>(EI);
    agg_kernel<<<(N_NODES + 7) / 8, 256>>>(X);
    wprep_kernel<<<256, 256>>>(W);
    gemm_mma_kernel<<<dim3(2, M_TILES), 256, SMEM_FLOATS * 4>>>(out);
}

// round 15
// speedup vs baseline: 2.3290x; 1.0869x over previous
#include <cuda_runtime.h>
#include <cstdint>

#define N_NODES 100000
#define E_EDGES 3200000
#define D 256
#define M_TILES 782            // ceil(100000/128)
#define M_PAD (M_TILES * 128)  // 100096 rows (padded; tail rows stay zero)

// ---------------- scratch (device globals: no allocation allowed) ----------
__device__ int   g_cnt[N_NODES];
__device__ float g_rdeg[N_NODES];
__device__ int   g_rowptr[N_NODES];
__device__ int   g_pos[N_NODES];
__device__ int   g_bsum[128];
__device__ int   g_bsumx[128];
__device__ int   g_adj[E_EDGES];           // dst packed by src (int32)
__device__ float g_A[(size_t)M_PAD * D];   // 102.5 MB aggregation buffer
// W in mma-fragment-major layout: [c(8)][nt(32)][ks(4)][lane(32)][4 regs]
// regs = (bh0, bh1, bl0, bl1); lane = (g*4+tg) ^ ks  (bank swizzle)
__device__ float g_FragB[8 * 32 * 4 * 32 * 4];   // 512 KB
__device__ int   g_is64;

// ---------------- dtype detection ------------------------------------------
// int64 edge values < 2^31 -> every odd 32-bit word is 0. int32 -> random.
__global__ void detect_kernel(const unsigned int* __restrict__ p) {
    __shared__ int any;
    if (threadIdx.x == 0) any = 0;
    __syncthreads();
    for (int k = threadIdx.x; k < 4096; k += blockDim.x) {
        size_t idx = 1 + 2ull * (size_t)k * 781ull;
        if (p[idx] != 0u) atomicOr(&any, 1);
    }
    __syncthreads();
    if (threadIdx.x == 0) g_is64 = any ? 0 : 1;
}

// ---------------- degree ----------------------------------------------------
__global__ void zero_cnt_kernel() {
    int i = blockIdx.x * blockDim.x + threadIdx.x;
    if (i < N_NODES) g_cnt[i] = 0;
}

__global__ void count_kernel(const void* __restrict__ ei) {
    const int is64 = g_is64;
    int stride = gridDim.x * blockDim.x;
    for (int e = blockIdx.x * blockDim.x + threadIdx.x; e < E_EDGES; e += stride) {
        int s = is64 ? (int)((const long long*)ei)[e] : ((const int*)ei)[e];
        atomicAdd(&g_cnt[s], 1);
    }
}

__global__ void rdeg_kernel() {
    int i = blockIdx.x * blockDim.x + threadIdx.x;
    if (i < N_NODES) g_rdeg[i] = 1.0f / (float)(g_cnt[i] + 1);
}

// ---------------- prefix scan of g_cnt -> g_rowptr (exclusive) -------------
__global__ void scan1_kernel() {
    __shared__ int ssum[256];
    int b = blockIdx.x, t = threadIdx.x;
    int base = b * 1024 + t * 4;
    int v[4];
    #pragma unroll
    for (int k = 0; k < 4; k++)
        v[k] = (base + k < N_NODES) ? g_cnt[base + k] : 0;
    int s = v[0] + v[1] + v[2] + v[3];
    ssum[t] = s;
    __syncthreads();
    #pragma unroll
    for (int off = 1; off < 256; off <<= 1) {
        int x = (t >= off) ? ssum[t - off] : 0;
        __syncthreads();
        ssum[t] += x;
        __syncthreads();
    }
    if (t == 255) g_bsum[b] = ssum[255];
    int run = ssum[t] - s;   // exclusive within block
    #pragma unroll
    for (int k = 0; k < 4; k++) {
        if (base + k < N_NODES) g_rowptr[base + k] = run;
        run += v[k];
    }
}

__global__ void scan2_kernel() {
    __shared__ int sb[128];
    int t = threadIdx.x;
    int nb = (N_NODES + 1023) / 1024;  // 98
    int orig = (t < nb) ? g_bsum[t] : 0;
    sb[t] = orig;
    __syncthreads();
    #pragma unroll
    for (int off = 1; off < 128; off <<= 1) {
        int x = (t >= off) ? sb[t - off] : 0;
        __syncthreads();
        sb[t] += x;
        __syncthreads();
    }
    g_bsumx[t] = sb[t] - orig;
}

__global__ void scan3_kernel() {
    int i = blockIdx.x * blockDim.x + threadIdx.x;
    if (i < N_NODES) {
        int rp = g_rowptr[i] + g_bsumx[i >> 10];
        g_rowptr[i] = rp;
        g_pos[i] = rp;
    }
}

// ---------------- scatter edges into CSR (dst as int32) ---------------------
__global__ void scatter_kernel(const void* __restrict__ ei) {
    const int is64 = g_is64;
    int stride = gridDim.x * blockDim.x;
    for (int e = blockIdx.x * blockDim.x + threadIdx.x; e < E_EDGES; e += stride) {
        int s, d;
        if (is64) {
            s = (int)((const long long*)ei)[e];
            d = (int)((const long long*)ei)[E_EDGES + e];
        } else {
            s = ((const int*)ei)[e];
            d = ((const int*)ei)[E_EDGES + e];
        }
        int p = atomicAdd(&g_pos[s], 1);
        g_adj[p] = d;
    }
}

// ---------------- aggregation: one warp per node, register accumulators -----
// A[i] = X[i]*rdeg[i] + sum_{j in adj(i)} X[j]*rdeg[j]
__device__ __forceinline__ void st_cs_v4(float* addr, float4 v) {
    asm volatile("st.global.cs.v4.f32 [%0], {%1, %2, %3, %4};"
                 :: "l"(addr), "f"(v.x), "f"(v.y), "f"(v.z), "f"(v.w)
                 : "memory");
}

__global__ __launch_bounds__(256) void agg_kernel(const float* __restrict__ X) {
    int w = blockIdx.x * 8 + (threadIdx.x >> 5);
    if (w >= N_NODES) return;
    const int lane = threadIdx.x & 31;
    const float4* X4 = (const float4*)X;

    float r = g_rdeg[w];
    float4 a0 = X4[(size_t)w * 64 + lane];
    float4 a1 = X4[(size_t)w * 64 + 32 + lane];
    a0.x *= r; a0.y *= r; a0.z *= r; a0.w *= r;
    a1.x *= r; a1.y *= r; a1.z *= r; a1.w *= r;

    int j   = g_rowptr[w];
    int end = j + g_cnt[w];
    int d0 = 0;
    if (j < end) d0 = g_adj[j];
    for (; j + 1 < end; j += 2) {
        int d1 = g_adj[j + 1];
        float r0 = g_rdeg[d0];
        float r1 = g_rdeg[d1];
        const float4* x0 = X4 + (size_t)d0 * 64;
        const float4* x1 = X4 + (size_t)d1 * 64;
        float4 v0 = __ldg(&x0[lane]);
        float4 v1 = __ldg(&x0[lane + 32]);
        float4 u0 = __ldg(&x1[lane]);
        float4 u1 = __ldg(&x1[lane + 32]);
        if (j + 2 < end) d0 = g_adj[j + 2];
        a0.x += v0.x * r0; a0.y += v0.y * r0; a0.z += v0.z * r0; a0.w += v0.w * r0;
        a1.x += v1.x * r0; a1.y += v1.y * r0; a1.z += v1.z * r0; a1.w += v1.w * r0;
        a0.x += u0.x * r1; a0.y += u0.y * r1; a0.z += u0.z * r1; a0.w += u0.w * r1;
        a1.x += u1.x * r1; a1.y += u1.y * r1; a1.z += u1.z * r1; a1.w += u1.w * r1;
    }
    if (j < end) {
        float r0 = g_rdeg[d0];
        const float4* x0 = X4 + (size_t)d0 * 64;
        float4 v0 = __ldg(&x0[lane]);
        float4 v1 = __ldg(&x0[lane + 32]);
        a0.x += v0.x * r0; a0.y += v0.y * r0; a0.z += v0.z * r0; a0.w += v0.w * r0;
        a1.x += v1.x * r0; a1.y += v1.y * r0; a1.z += v1.z * r0; a1.w += v1.w * r0;
    }
    float* ar = g_A + (size_t)w * D;
    st_cs_v4(ar + lane * 4, a0);
    st_cs_v4(ar + (lane + 32) * 4, a1);
}

// ---------------- W prep: tf32 hi/lo split into fragment-major layout -------
__global__ void wprep_kernel(const float* __restrict__ W) {
    int idx = blockIdx.x * blockDim.x + threadIdx.x;   // 0..65535 = k*256+n
    int k = idx >> 8;
    int n = idx & 255;
    float w  = W[idx];
    float hi = __uint_as_float(__float_as_uint(w) & 0xFFFFE000u);
    float lo = w - hi;
    int c = k >> 5, kk = k & 31, ks = kk >> 3, t = kk & 7;
    int tg = t & 3, half = t >> 2;
    int nt = n >> 3, g = n & 7;
    int lane = (g * 4 + tg) ^ ks;                      // bank swizzle
    size_t fi = ((((size_t)c * 32 + nt) * 4 + ks) * 32 + lane) * 4 + half;
    g_FragB[fi]     = hi;   // regs 0,1 = bh0(k+tg), bh1(k+tg+4)
    g_FragB[fi + 2] = lo;   // regs 2,3 = bl0, bl1
}

// ---------------- GEMM: out = A @ W via mma.sync tf32 (3xTF32) --------------
// CTA 128x128, 8 warps 4x2, warp tile 32x64, BK=32, 8 K-chunks.
// Fragment-major SMEM, cp.async double-buffered B, register-pipelined A.
#define SM_AH_F 0
#define SM_AL_F 4096
#define SM_B0_F 8192
#define SM_B1_F 16384
#define SMEM_FLOATS (8192 + 16384)   // 24576 floats = 96 KB

#define CP_ASYNC16(smem_u32, gptr) \
    asm volatile("cp.async.ca.shared.global [%0], [%1], 16;" \
                 :: "r"(smem_u32), "l"(gptr) : "memory")
#define CP_COMMIT() asm volatile("cp.async.commit_group;" ::: "memory")
#define CP_WAIT0()  asm volatile("cp.async.wait_group 0;" ::: "memory")
#define CP_WAIT1()  asm volatile("cp.async.wait_group 1;" ::: "memory")

__device__ __forceinline__ void mma_tf32(float* c, const float4 a, float b0, float b1) {
    asm volatile(
        "mma.sync.aligned.m16n8k8.row.col.f32.tf32.tf32.f32 "
        "{%0,%1,%2,%3}, {%4,%5,%6,%7}, {%8,%9}, {%0,%1,%2,%3};"
        : "+f"(c[0]), "+f"(c[1]), "+f"(c[2]), "+f"(c[3])
        : "r"(__float_as_uint(a.x)), "r"(__float_as_uint(a.y)),
          "r"(__float_as_uint(a.z)), "r"(__float_as_uint(a.w)),
          "r"(__float_as_uint(b0)), "r"(__float_as_uint(b1)));
}

__global__ __launch_bounds__(256) void gemm_mma_kernel(float* __restrict__ out) {
    extern __shared__ float smem[];
    float* AH = smem + SM_AH_F;
    float* AL = smem + SM_AL_F;

    const int tid  = threadIdx.x;
    const int wid  = tid >> 5;
    const int lane = tid & 31;
    const int g    = lane >> 2;
    const int tg   = lane & 3;
    const int wm   = wid >> 1;       // 0..3
    const int wn   = wid & 1;        // 0..1

    const size_t rowBase = (size_t)blockIdx.y * 128;
    const int    bx      = blockIdx.x;            // N tile 0..1
    const int    colBase = bx * 128;
    const float* Atile = g_A + rowBase * D;

    // per-thread A load coords: 4 float4 per chunk (rows ar+32i, cols ac4..ac4+3)
    const int ar = tid >> 3;              // 0..31
    const int ac4 = (tid & 7) * 4;        // 0,4,...,28

    float acc[2][8][4];
    #pragma unroll
    for (int i = 0; i < 2; i++)
        #pragma unroll
        for (int j = 0; j < 8; j++)
            #pragma unroll
            for (int k = 0; k < 4; k++) acc[i][j][k] = 0.f;

    // ---- B cp.async: 2048 float4 per chunk, 8 per thread ----
    uint32_t sB[2];
    sB[0] = (uint32_t)__cvta_generic_to_shared(smem + SM_B0_F);
    sB[1] = (uint32_t)__cvta_generic_to_shared(smem + SM_B1_F);
    const float4* FB = (const float4*)g_FragB;

    auto cpB = [&](int c, int buf) {
        const float4* src = FB + ((size_t)(c * 32 + bx * 16)) * 128 + tid;
        uint32_t dst = sB[buf] + tid * 16;
        #pragma unroll
        for (int i = 0; i < 8; i++)
            CP_ASYNC16(dst + i * 4096, (const void*)(src + i * 256));
    };

    float4 pa[4];
    auto loadA = [&](int c) {
        #pragma unroll
        for (int i = 0; i < 4; i++)
            pa[i] = *(const float4*)(Atile + (size_t)(ar + i * 32) * D + c * 32 + ac4);
    };

    // prologue
    cpB(0, 0); CP_COMMIT();
    loadA(0);

    #pragma unroll 1
    for (int c = 0; c < 8; c++) {
        // ---- split A chunk into fragment-major SMEM ----
        {
            const int ks   = ac4 >> 3;
            const int half = (ac4 >> 2) & 1;
            #pragma unroll
            for (int i = 0; i < 4; i++) {
                int r  = ar + i * 32;
                int m  = r >> 4;
                int r8 = (r >> 3) & 1;
                int gg = r & 7;
                int reg = half * 2 + r8;
                int base = (m * 4 + ks) * 32;
                float4 v = pa[i];
                uint4 u = *(uint4*)&v;
                float h0 = __uint_as_float(u.x & 0xFFFFE000u);
                float h1 = __uint_as_float(u.y & 0xFFFFE000u);
                float h2 = __uint_as_float(u.z & 0xFFFFE000u);
                float h3 = __uint_as_float(u.w & 0xFFFFE000u);
                int L0 = (gg * 4 + 0) ^ ks;
                int L1 = (gg * 4 + 1) ^ ks;
                int L2 = (gg * 4 + 2) ^ ks;
                int L3 = (gg * 4 + 3) ^ ks;
                AH[(base + L0) * 4 + reg] = h0;
                AH[(base + L1) * 4 + reg] = h1;
                AH[(base + L2) * 4 + reg] = h2;
                AH[(base + L3) * 4 + reg] = h3;
                AL[(base + L0) * 4 + reg] = v.x - h0;
                AL[(base + L1) * 4 + reg] = v.y - h1;
                AL[(base + L2) * 4 + reg] = v.z - h2;
                AL[(base + L3) * 4 + reg] = v.w - h3;
            }
        }
        // ---- prefetch next chunk ----
        if (c < 7) {
            cpB(c + 1, (c + 1) & 1); CP_COMMIT();
            loadA(c + 1);
            CP_WAIT1();
        } else {
            CP_WAIT0();
        }
        __syncthreads();

        // ---- MMA loop on chunk c ----
        const float* BF = smem + (((c & 1) == 0) ? SM_B0_F : SM_B1_F);
        #pragma unroll
        for (int ks = 0; ks < 4; ks++) {
            const int Ls = lane ^ ks;
            float4 ah[2], al[2];
            #pragma unroll
            for (int mt = 0; mt < 2; mt++) {
                int m = wm * 2 + mt;
                ah[mt] = *(const float4*)(AH + ((m * 4 + ks) * 32 + Ls) * 4);
                al[mt] = *(const float4*)(AL + ((m * 4 + ks) * 32 + Ls) * 4);
            }
            #pragma unroll
            for (int nt = 0; nt < 8; nt++) {
                int ntl = wn * 8 + nt;
                float4 b = *(const float4*)(BF + ((ntl * 4 + ks) * 32 + Ls) * 4);
                #pragma unroll
                for (int mt = 0; mt < 2; mt++) {
                    mma_tf32(acc[mt][nt], ah[mt], b.x, b.y);   // hi*hi
                    mma_tf32(acc[mt][nt], ah[mt], b.z, b.w);   // hi*lo
                    mma_tf32(acc[mt][nt], al[mt], b.x, b.y);   // lo*hi
                }
            }
        }
        __syncthreads();
    }

    // ---- epilogue ----
    #pragma unroll
    for (int mt = 0; mt < 2; mt++) {
        size_t r0 = rowBase + wm * 32 + mt * 16 + g;
        #pragma unroll
        for (int nt = 0; nt < 8; nt++) {
            int col = colBase + wn * 64 + nt * 8 + tg * 2;
            if (r0 < N_NODES)
                *(float2*)(out + r0 * D + col) = make_float2(acc[mt][nt][0], acc[mt][nt][1]);
            if (r0 + 8 < N_NODES)
                *(float2*)(out + (r0 + 8) * D + col) = make_float2(acc[mt][nt][2], acc[mt][nt][3]);
        }
    }
}

// ---------------- launch ----------------------------------------------------
extern "C" void kernel_launch(void* const* d_in, const int* in_sizes, int n_in,
                              void* d_out, int out_size) {
    const float* X  = (const float*)d_in[0];
    const void*  EI = d_in[1];
    const float* W  = (const float*)d_in[2];
    float*       out = (float*)d_out;

    cudaFuncSetAttribute(gemm_mma_kernel,
                         cudaFuncAttributeMaxDynamicSharedMemorySize,
                         SMEM_FLOATS * 4);

    detect_kernel<<<1, 256>>>((const unsigned int*)EI);
    zero_cnt_kernel<<<(N_NODES + 255) / 256, 256>>>();
    count_kernel<<<4096, 256>>>(EI);
    rdeg_kernel<<<(N_NODES + 255) / 256, 256>>>();
    scan1_kernel<<<(N_NODES + 1023) / 1024, 256>>>();
    scan2_kernel<<<1, 128>>>();
    scan3_kernel<<<(N_NODES + 255) / 256, 256>>>();
    scatter_kernel<<<4096, 256>>>(EI);
    agg_kernel<<<(N_NODES + 7) / 8, 256>>>(X);
    wprep_kernel<<<256, 256>>>(W);
    gemm_mma_kernel<<<dim3(2, M_TILES), 256, SMEM_FLOATS * 4>>>(out);
}

// round 16
// speedup vs baseline: 2.6535x; 1.1393x over previous
#include <cuda_runtime.h>
#include <cuda_fp16.h>
#include <cstdint>

#define N_NODES 100000
#define E_EDGES 3200000
#define D 256
#define M_TILES 782            // ceil(100000/128)
#define M_PAD (M_TILES * 128)  // 100096 rows (padded; tail rows stay zero)

// ---------------- scratch (device globals: no allocation allowed) ----------
__device__ int   g_cnt[N_NODES];
__device__ float g_rdeg[N_NODES];
__device__ int   g_rowptr[N_NODES];
__device__ int   g_pos[N_NODES];
__device__ int   g_bsum[128];
__device__ int   g_bsumx[128];
__device__ int   g_adj[E_EDGES];           // dst packed by src (int32)
__device__ __half g_Xh[(size_t)N_NODES * D];  // X in fp16 (51.2 MB, L2-resident)
__device__ float g_A[(size_t)M_PAD * D];   // 102.5 MB aggregation buffer
// W in mma-fragment-major layout: [c(8)][nt(32)][ks(4)][lane(32)][4 regs]
// regs = (bh0, bh1, bl0, bl1); lane = (g*4+tg) ^ ks  (bank swizzle)
__device__ float g_FragB[8 * 32 * 4 * 32 * 4];   // 512 KB
__device__ int   g_is64;

// ---------------- dtype detection ------------------------------------------
// int64 edge values < 2^31 -> every odd 32-bit word is 0. int32 -> random.
__global__ void detect_kernel(const unsigned int* __restrict__ p) {
    __shared__ int any;
    if (threadIdx.x == 0) any = 0;
    __syncthreads();
    for (int k = threadIdx.x; k < 4096; k += blockDim.x) {
        size_t idx = 1 + 2ull * (size_t)k * 781ull;
        if (p[idx] != 0u) atomicOr(&any, 1);
    }
    __syncthreads();
    if (threadIdx.x == 0) g_is64 = any ? 0 : 1;
}

// ---------------- degree ----------------------------------------------------
__global__ void zero_cnt_kernel() {
    int i = blockIdx.x * blockDim.x + threadIdx.x;
    if (i < N_NODES) g_cnt[i] = 0;
}

__global__ void count_kernel(const void* __restrict__ ei) {
    const int is64 = g_is64;
    int stride = gridDim.x * blockDim.x;
    for (int e = blockIdx.x * blockDim.x + threadIdx.x; e < E_EDGES; e += stride) {
        int s = is64 ? (int)((const long long*)ei)[e] : ((const int*)ei)[e];
        atomicAdd(&g_cnt[s], 1);
    }
}

__global__ void rdeg_kernel() {
    int i = blockIdx.x * blockDim.x + threadIdx.x;
    if (i < N_NODES) g_rdeg[i] = 1.0f / (float)(g_cnt[i] + 1);
}

// ---------------- X -> fp16 conversion --------------------------------------
// 25.6M elements, 8 per thread (two float4 -> one uint4 of 8 halves)
__global__ void xprep_kernel(const float* __restrict__ X) {
    int i = blockIdx.x * blockDim.x + threadIdx.x;    // 0 .. 3.2M-1
    if (i >= N_NODES * (D / 8)) return;
    const float4* X4 = (const float4*)X;
    float4 v0 = X4[i * 2];
    float4 v1 = X4[i * 2 + 1];
    __half2 h[4];
    h[0] = __float22half2_rn(make_float2(v0.x, v0.y));
    h[1] = __float22half2_rn(make_float2(v0.z, v0.w));
    h[2] = __float22half2_rn(make_float2(v1.x, v1.y));
    h[3] = __float22half2_rn(make_float2(v1.z, v1.w));
    ((uint4*)g_Xh)[i] = *(uint4*)h;
}

// ---------------- prefix scan of g_cnt -> g_rowptr (exclusive) -------------
__global__ void scan1_kernel() {
    __shared__ int ssum[256];
    int b = blockIdx.x, t = threadIdx.x;
    int base = b * 1024 + t * 4;
    int v[4];
    #pragma unroll
    for (int k = 0; k < 4; k++)
        v[k] = (base + k < N_NODES) ? g_cnt[base + k] : 0;
    int s = v[0] + v[1] + v[2] + v[3];
    ssum[t] = s;
    __syncthreads();
    #pragma unroll
    for (int off = 1; off < 256; off <<= 1) {
        int x = (t >= off) ? ssum[t - off] : 0;
        __syncthreads();
        ssum[t] += x;
        __syncthreads();
    }
    if (t == 255) g_bsum[b] = ssum[255];
    int run = ssum[t] - s;   // exclusive within block
    #pragma unroll
    for (int k = 0; k < 4; k++) {
        if (base + k < N_NODES) g_rowptr[base + k] = run;
        run += v[k];
    }
}

__global__ void scan2_kernel() {
    __shared__ int sb[128];
    int t = threadIdx.x;
    int nb = (N_NODES + 1023) / 1024;  // 98
    int orig = (t < nb) ? g_bsum[t] : 0;
    sb[t] = orig;
    __syncthreads();
    #pragma unroll
    for (int off = 1; off < 128; off <<= 1) {
        int x = (t >= off) ? sb[t - off] : 0;
        __syncthreads();
        sb[t] += x;
        __syncthreads();
    }
    g_bsumx[t] = sb[t] - orig;
}

__global__ void scan3_kernel() {
    int i = blockIdx.x * blockDim.x + threadIdx.x;
    if (i < N_NODES) {
        int rp = g_rowptr[i] + g_bsumx[i >> 10];
        g_rowptr[i] = rp;
        g_pos[i] = rp;
    }
}

// ---------------- scatter edges into CSR (dst as int32) ---------------------
__global__ void scatter_kernel(const void* __restrict__ ei) {
    const int is64 = g_is64;
    int stride = gridDim.x * blockDim.x;
    for (int e = blockIdx.x * blockDim.x + threadIdx.x; e < E_EDGES; e += stride) {
        int s, d;
        if (is64) {
            s = (int)((const long long*)ei)[e];
            d = (int)((const long long*)ei)[E_EDGES + e];
        } else {
            s = ((const int*)ei)[e];
            d = ((const int*)ei)[E_EDGES + e];
        }
        int p = atomicAdd(&g_pos[s], 1);
        g_adj[p] = d;
    }
}

// ---------------- aggregation: one warp per node, fp16 gathers --------------
// A[i] = X[i]*rdeg[i] + sum_{j in adj(i)} X[j]*rdeg[j]
// Each lane owns 8 consecutive cols (lane*8..lane*8+7); one LDG.128 per row.
__device__ __forceinline__ void st_cs_v4(float* addr, float4 v) {
    asm volatile("st.global.cs.v4.f32 [%0], {%1, %2, %3, %4};"
                 :: "l"(addr), "f"(v.x), "f"(v.y), "f"(v.z), "f"(v.w)
                 : "memory");
}

__device__ __forceinline__ void acc8(float* a, uint4 raw, float r) {
    __half2* h = (__half2*)&raw;
    float2 f0 = __half22float2(h[0]);
    float2 f1 = __half22float2(h[1]);
    float2 f2 = __half22float2(h[2]);
    float2 f3 = __half22float2(h[3]);
    a[0] += f0.x * r; a[1] += f0.y * r;
    a[2] += f1.x * r; a[3] += f1.y * r;
    a[4] += f2.x * r; a[5] += f2.y * r;
    a[6] += f3.x * r; a[7] += f3.y * r;
}

__global__ __launch_bounds__(256) void agg_kernel() {
    int w = blockIdx.x * 8 + (threadIdx.x >> 5);
    if (w >= N_NODES) return;
    const int lane = threadIdx.x & 31;
    const uint4* Xh = (const uint4*)g_Xh;   // row = 32 uint4s (512 B)

    float a[8] = {};
    float r = g_rdeg[w];
    acc8(a, Xh[(size_t)w * 32 + lane], r);  // self-loop term

    int j   = g_rowptr[w];
    int end = j + g_cnt[w];
    int d0 = 0;
    if (j < end) d0 = g_adj[j];
    for (; j + 1 < end; j += 2) {
        int d1 = g_adj[j + 1];
        float r0 = g_rdeg[d0];
        float r1 = g_rdeg[d1];
        uint4 v0 = __ldg(&Xh[(size_t)d0 * 32 + lane]);
        uint4 v1 = __ldg(&Xh[(size_t)d1 * 32 + lane]);
        if (j + 2 < end) d0 = g_adj[j + 2];
        acc8(a, v0, r0);
        acc8(a, v1, r1);
    }
    if (j < end) {
        float r0 = g_rdeg[d0];
        uint4 v0 = __ldg(&Xh[(size_t)d0 * 32 + lane]);
        acc8(a, v0, r0);
    }

    float* ar = g_A + (size_t)w * D + lane * 8;
    st_cs_v4(ar,     make_float4(a[0], a[1], a[2], a[3]));
    st_cs_v4(ar + 4, make_float4(a[4], a[5], a[6], a[7]));
}

// ---------------- W prep: tf32 hi/lo split into fragment-major layout -------
__global__ void wprep_kernel(const float* __restrict__ W) {
    int idx = blockIdx.x * blockDim.x + threadIdx.x;   // 0..65535 = k*256+n
    int k = idx >> 8;
    int n = idx & 255;
    float w  = W[idx];
    float hi = __uint_as_float(__float_as_uint(w) & 0xFFFFE000u);
    float lo = w - hi;
    int c = k >> 5, kk = k & 31, ks = kk >> 3, t = kk & 7;
    int tg = t & 3, half = t >> 2;
    int nt = n >> 3, g = n & 7;
    int lane = (g * 4 + tg) ^ ks;                      // bank swizzle
    size_t fi = ((((size_t)c * 32 + nt) * 4 + ks) * 32 + lane) * 4 + half;
    g_FragB[fi]     = hi;   // regs 0,1 = bh0(k+tg), bh1(k+tg+4)
    g_FragB[fi + 2] = lo;   // regs 2,3 = bl0, bl1
}

// ---------------- GEMM: out = A @ W via mma.sync tf32 (3xTF32) --------------
// CTA 128x128, 8 warps 4x2, warp tile 32x64, BK=32, 8 K-chunks.
// Fragment-major SMEM, cp.async double-buffered B, register-pipelined A.
#define SM_AH_F 0
#define SM_AL_F 4096
#define SM_B0_F 8192
#define SM_B1_F 16384
#define SMEM_FLOATS (8192 + 16384)   // 24576 floats = 96 KB

#define CP_ASYNC16(smem_u32, gptr) \
    asm volatile("cp.async.ca.shared.global [%0], [%1], 16;" \
                 :: "r"(smem_u32), "l"(gptr) : "memory")
#define CP_COMMIT() asm volatile("cp.async.commit_group;" ::: "memory")
#define CP_WAIT0()  asm volatile("cp.async.wait_group 0;" ::: "memory")
#define CP_WAIT1()  asm volatile("cp.async.wait_group 1;" ::: "memory")

__device__ __forceinline__ void mma_tf32(float* c, const float4 a, float b0, float b1) {
    asm volatile(
        "mma.sync.aligned.m16n8k8.row.col.f32.tf32.tf32.f32 "
        "{%0,%1,%2,%3}, {%4,%5,%6,%7}, {%8,%9}, {%0,%1,%2,%3};"
        : "+f"(c[0]), "+f"(c[1]), "+f"(c[2]), "+f"(c[3])
        : "r"(__float_as_uint(a.x)), "r"(__float_as_uint(a.y)),
          "r"(__float_as_uint(a.z)), "r"(__float_as_uint(a.w)),
          "r"(__float_as_uint(b0)), "r"(__float_as_uint(b1)));
}

__global__ __launch_bounds__(256) void gemm_mma_kernel(float* __restrict__ out) {
    extern __shared__ float smem[];
    float* AH = smem + SM_AH_F;
    float* AL = smem + SM_AL_F;

    const int tid  = threadIdx.x;
    const int wid  = tid >> 5;
    const int lane = tid & 31;
    const int g    = lane >> 2;
    const int tg   = lane & 3;
    const int wm   = wid >> 1;       // 0..3
    const int wn   = wid & 1;        // 0..1

    const size_t rowBase = (size_t)blockIdx.y * 128;
    const int    bx      = blockIdx.x;            // N tile 0..1
    const int    colBase = bx * 128;
    const float* Atile = g_A + rowBase * D;

    // per-thread A load coords: 4 float4 per chunk (rows ar+32i, cols ac4..ac4+3)
    const int ar = tid >> 3;              // 0..31
    const int ac4 = (tid & 7) * 4;        // 0,4,...,28

    float acc[2][8][4];
    #pragma unroll
    for (int i = 0; i < 2; i++)
        #pragma unroll
        for (int j = 0; j < 8; j++)
            #pragma unroll
            for (int k = 0; k < 4; k++) acc[i][j][k] = 0.f;

    // ---- B cp.async: 2048 float4 per chunk, 8 per thread ----
    uint32_t sB[2];
    sB[0] = (uint32_t)__cvta_generic_to_shared(smem + SM_B0_F);
    sB[1] = (uint32_t)__cvta_generic_to_shared(smem + SM_B1_F);
    const float4* FB = (const float4*)g_FragB;

    auto cpB = [&](int c, int buf) {
        const float4* src = FB + ((size_t)(c * 32 + bx * 16)) * 128 + tid;
        uint32_t dst = sB[buf] + tid * 16;
        #pragma unroll
        for (int i = 0; i < 8; i++)
            CP_ASYNC16(dst + i * 4096, (const void*)(src + i * 256));
    };

    float4 pa[4];
    auto loadA = [&](int c) {
        #pragma unroll
        for (int i = 0; i < 4; i++)
            pa[i] = *(const float4*)(Atile + (size_t)(ar + i * 32) * D + c * 32 + ac4);
    };

    // prologue
    cpB(0, 0); CP_COMMIT();
    loadA(0);

    #pragma unroll 1
    for (int c = 0; c < 8; c++) {
        // ---- split A chunk into fragment-major SMEM ----
        {
            const int ks   = ac4 >> 3;
            const int half = (ac4 >> 2) & 1;
            #pragma unroll
            for (int i = 0; i < 4; i++) {
                int r  = ar + i * 32;
                int m  = r >> 4;
                int r8 = (r >> 3) & 1;
                int gg = r & 7;
                int reg = half * 2 + r8;
                int base = (m * 4 + ks) * 32;
                float4 v = pa[i];
                uint4 u = *(uint4*)&v;
                float h0 = __uint_as_float(u.x & 0xFFFFE000u);
                float h1 = __uint_as_float(u.y & 0xFFFFE000u);
                float h2 = __uint_as_float(u.z & 0xFFFFE000u);
                float h3 = __uint_as_float(u.w & 0xFFFFE000u);
                int L0 = (gg * 4 + 0) ^ ks;
                int L1 = (gg * 4 + 1) ^ ks;
                int L2 = (gg * 4 + 2) ^ ks;
                int L3 = (gg * 4 + 3) ^ ks;
                AH[(base + L0) * 4 + reg] = h0;
                AH[(base + L1) * 4 + reg] = h1;
                AH[(base + L2) * 4 + reg] = h2;
                AH[(base + L3) * 4 + reg] = h3;
                AL[(base + L0) * 4 + reg] = v.x - h0;
                AL[(base + L1) * 4 + reg] = v.y - h1;
                AL[(base + L2) * 4 + reg] = v.z - h2;
                AL[(base + L3) * 4 + reg] = v.w - h3;
            }
        }
        // ---- prefetch next chunk ----
        if (c < 7) {
            cpB(c + 1, (c + 1) & 1); CP_COMMIT();
            loadA(c + 1);
            CP_WAIT1();
        } else {
            CP_WAIT0();
        }
        __syncthreads();

        // ---- MMA loop on chunk c ----
        const float* BF = smem + (((c & 1) == 0) ? SM_B0_F : SM_B1_F);
        #pragma unroll
        for (int ks = 0; ks < 4; ks++) {
            const int Ls = lane ^ ks;
            float4 ah[2], al[2];
            #pragma unroll
            for (int mt = 0; mt < 2; mt++) {
                int m = wm * 2 + mt;
                ah[mt] = *(const float4*)(AH + ((m * 4 + ks) * 32 + Ls) * 4);
                al[mt] = *(const float4*)(AL + ((m * 4 + ks) * 32 + Ls) * 4);
            }
            #pragma unroll
            for (int nt = 0; nt < 8; nt++) {
                int ntl = wn * 8 + nt;
                float4 b = *(const float4*)(BF + ((ntl * 4 + ks) * 32 + Ls) * 4);
                #pragma unroll
                for (int mt = 0; mt < 2; mt++) {
                    mma_tf32(acc[mt][nt], ah[mt], b.x, b.y);   // hi*hi
                    mma_tf32(acc[mt][nt], ah[mt], b.z, b.w);   // hi*lo
                    mma_tf32(acc[mt][nt], al[mt], b.x, b.y);   // lo*hi
                }
            }
        }
        __syncthreads();
    }

    // ---- epilogue ----
    #pragma unroll
    for (int mt = 0; mt < 2; mt++) {
        size_t r0 = rowBase + wm * 32 + mt * 16 + g;
        #pragma unroll
        for (int nt = 0; nt < 8; nt++) {
            int col = colBase + wn * 64 + nt * 8 + tg * 2;
            if (r0 < N_NODES)
                *(float2*)(out + r0 * D + col) = make_float2(acc[mt][nt][0], acc[mt][nt][1]);
            if (r0 + 8 < N_NODES)
                *(float2*)(out + (r0 + 8) * D + col) = make_float2(acc[mt][nt][2], acc[mt][nt][3]);
        }
    }
}

// ---------------- launch ----------------------------------------------------
extern "C" void kernel_launch(void* const* d_in, const int* in_sizes, int n_in,
                              void* d_out, int out_size) {
    const float* X  = (const float*)d_in[0];
    const void*  EI = d_in[1];
    const float* W  = (const float*)d_in[2];
    float*       out = (float*)d_out;

    cudaFuncSetAttribute(gemm_mma_kernel,
                         cudaFuncAttributeMaxDynamicSharedMemorySize,
                         SMEM_FLOATS * 4);

    detect_kernel<<<1, 256>>>((const unsigned int*)EI);
    zero_cnt_kernel<<<(N_NODES + 255) / 256, 256>>>();
    count_kernel<<<4096, 256>>>(EI);
    rdeg_kernel<<<(N_NODES + 255) / 256, 256>>>();
    xprep_kernel<<<(N_NODES * (D / 8) + 255) / 256, 256>>>(X);
    scan1_kernel<<<(N_NODES + 1023) / 1024, 256>>>();
    scan2_kernel<<<1, 128>>>();
    scan3_kernel<<<(N_NODES + 255) / 256, 256>>>();
    scatter_kernel<<<4096, 256>>>(EI);
    agg_kernel<<<(N_NODES + 7) / 8, 256>>>();
    wprep_kernel<<<256, 256>>>(W);
    gemm_mma_kernel<<<dim3(2, M_TILES), 256, SMEM_FLOATS * 4>>>(out);
}

// round 17
// speedup vs baseline: 3.5511x; 1.3383x over previous
#include <cuda_runtime.h>
#include <cuda_fp16.h>
#include <cstdint>

#define N_NODES 100000
#define E_EDGES 3200000
#define D 256
#define M_TILES 782            // ceil(100000/128)
#define M_PAD (M_TILES * 128)  // 100096 rows (padded; tail rows stay zero)

// ---------------- scratch (device globals: no allocation allowed) ----------
__device__ int   g_cnt[N_NODES];
__device__ float g_rdeg[N_NODES];
__device__ int   g_rowptr[N_NODES];
__device__ int   g_pos[N_NODES];
__device__ int   g_bsum[128];
__device__ int   g_bsumx[128];
__device__ int   g_adj[E_EDGES];              // dst packed by src (int32)
__device__ __half g_Xh[(size_t)N_NODES * D];  // X in fp16 (51.2 MB)
__device__ __half g_Ah[(size_t)M_PAD * D];    // A in fp16 (51.2 MB; tail rows zero)
// W 2xfp16 split, mma-fragment-major: [c(4)][nt(32)][ks(4)][lane(32)][4 b32]
// b32 words = (bh0, bh1, bl0, bl1); lane = (g*4+tg) ^ ks  (bank swizzle)
__device__ __half g_FragBh[4 * 32 * 4 * 32 * 8];   // 256 KB
__device__ int   g_is64;

// ---------------- dtype detection ------------------------------------------
// int64 edge values < 2^31 -> every odd 32-bit word is 0. int32 -> random.
__global__ void detect_kernel(const unsigned int* __restrict__ p) {
    __shared__ int any;
    if (threadIdx.x == 0) any = 0;
    __syncthreads();
    for (int k = threadIdx.x; k < 4096; k += blockDim.x) {
        size_t idx = 1 + 2ull * (size_t)k * 781ull;
        if (p[idx] != 0u) atomicOr(&any, 1);
    }
    __syncthreads();
    if (threadIdx.x == 0) g_is64 = any ? 0 : 1;
}

// ---------------- degree ----------------------------------------------------
__global__ void zero_cnt_kernel() {
    int i = blockIdx.x * blockDim.x + threadIdx.x;
    if (i < N_NODES) g_cnt[i] = 0;
}

__global__ void count_kernel(const void* __restrict__ ei) {
    const int is64 = g_is64;
    int stride = gridDim.x * blockDim.x;
    for (int e = blockIdx.x * blockDim.x + threadIdx.x; e < E_EDGES; e += stride) {
        int s = is64 ? (int)((const long long*)ei)[e] : ((const int*)ei)[e];
        atomicAdd(&g_cnt[s], 1);
    }
}

__global__ void rdeg_kernel() {
    int i = blockIdx.x * blockDim.x + threadIdx.x;
    if (i < N_NODES) g_rdeg[i] = 1.0f / (float)(g_cnt[i] + 1);
}

// ---------------- X -> fp16 conversion --------------------------------------
__global__ void xprep_kernel(const float* __restrict__ X) {
    int i = blockIdx.x * blockDim.x + threadIdx.x;    // 0 .. 3.2M-1
    if (i >= N_NODES * (D / 8)) return;
    const float4* X4 = (const float4*)X;
    float4 v0 = X4[i * 2];
    float4 v1 = X4[i * 2 + 1];
    __half2 h[4];
    h[0] = __float22half2_rn(make_float2(v0.x, v0.y));
    h[1] = __float22half2_rn(make_float2(v0.z, v0.w));
    h[2] = __float22half2_rn(make_float2(v1.x, v1.y));
    h[3] = __float22half2_rn(make_float2(v1.z, v1.w));
    ((uint4*)g_Xh)[i] = *(uint4*)h;
}

// ---------------- prefix scan of g_cnt -> g_rowptr (exclusive) -------------
__global__ void scan1_kernel() {
    __shared__ int ssum[256];
    int b = blockIdx.x, t = threadIdx.x;
    int base = b * 1024 + t * 4;
    int v[4];
    #pragma unroll
    for (int k = 0; k < 4; k++)
        v[k] = (base + k < N_NODES) ? g_cnt[base + k] : 0;
    int s = v[0] + v[1] + v[2] + v[3];
    ssum[t] = s;
    __syncthreads();
    #pragma unroll
    for (int off = 1; off < 256; off <<= 1) {
        int x = (t >= off) ? ssum[t - off] : 0;
        __syncthreads();
        ssum[t] += x;
        __syncthreads();
    }
    if (t == 255) g_bsum[b] = ssum[255];
    int run = ssum[t] - s;   // exclusive within block
    #pragma unroll
    for (int k = 0; k < 4; k++) {
        if (base + k < N_NODES) g_rowptr[base + k] = run;
        run += v[k];
    }
}

__global__ void scan2_kernel() {
    __shared__ int sb[128];
    int t = threadIdx.x;
    int nb = (N_NODES + 1023) / 1024;  // 98
    int orig = (t < nb) ? g_bsum[t] : 0;
    sb[t] = orig;
    __syncthreads();
    #pragma unroll
    for (int off = 1; off < 128; off <<= 1) {
        int x = (t >= off) ? sb[t - off] : 0;
        __syncthreads();
        sb[t] += x;
        __syncthreads();
    }
    g_bsumx[t] = sb[t] - orig;
}

__global__ void scan3_kernel() {
    int i = blockIdx.x * blockDim.x + threadIdx.x;
    if (i < N_NODES) {
        int rp = g_rowptr[i] + g_bsumx[i >> 10];
        g_rowptr[i] = rp;
        g_pos[i] = rp;
    }
}

// ---------------- scatter edges into CSR (dst as int32) ---------------------
__global__ void scatter_kernel(const void* __restrict__ ei) {
    const int is64 = g_is64;
    int stride = gridDim.x * blockDim.x;
    for (int e = blockIdx.x * blockDim.x + threadIdx.x; e < E_EDGES; e += stride) {
        int s, d;
        if (is64) {
            s = (int)((const long long*)ei)[e];
            d = (int)((const long long*)ei)[E_EDGES + e];
        } else {
            s = ((const int*)ei)[e];
            d = ((const int*)ei)[E_EDGES + e];
        }
        int p = atomicAdd(&g_pos[s], 1);
        g_adj[p] = d;
    }
}

// ---------------- aggregation: one warp per node, fp16 gathers, fp16 store --
// A[i] = X[i]*rdeg[i] + sum_{j in adj(i)} X[j]*rdeg[j]
__device__ __forceinline__ void acc8(float* a, uint4 raw, float r) {
    __half2* h = (__half2*)&raw;
    float2 f0 = __half22float2(h[0]);
    float2 f1 = __half22float2(h[1]);
    float2 f2 = __half22float2(h[2]);
    float2 f3 = __half22float2(h[3]);
    a[0] += f0.x * r; a[1] += f0.y * r;
    a[2] += f1.x * r; a[3] += f1.y * r;
    a[4] += f2.x * r; a[5] += f2.y * r;
    a[6] += f3.x * r; a[7] += f3.y * r;
}

__global__ __launch_bounds__(256) void agg_kernel() {
    int w = blockIdx.x * 8 + (threadIdx.x >> 5);
    if (w >= N_NODES) return;
    const int lane = threadIdx.x & 31;
    const uint4* Xh = (const uint4*)g_Xh;   // row = 32 uint4s (512 B)

    float a[8] = {};
    float r = g_rdeg[w];
    acc8(a, Xh[(size_t)w * 32 + lane], r);  // self-loop term

    int j   = g_rowptr[w];
    int end = j + g_cnt[w];
    int d0 = 0;
    if (j < end) d0 = g_adj[j];
    for (; j + 1 < end; j += 2) {
        int d1 = g_adj[j + 1];
        float r0 = g_rdeg[d0];
        float r1 = g_rdeg[d1];
        uint4 v0 = __ldg(&Xh[(size_t)d0 * 32 + lane]);
        uint4 v1 = __ldg(&Xh[(size_t)d1 * 32 + lane]);
        if (j + 2 < end) d0 = g_adj[j + 2];
        acc8(a, v0, r0);
        acc8(a, v1, r1);
    }
    if (j < end) {
        float r0 = g_rdeg[d0];
        uint4 v0 = __ldg(&Xh[(size_t)d0 * 32 + lane]);
        acc8(a, v0, r0);
    }

    // pack 8 fp32 -> 8 fp16, one 16B evict-first store
    __half2 h[4];
    h[0] = __floats2half2_rn(a[0], a[1]);
    h[1] = __floats2half2_rn(a[2], a[3]);
    h[2] = __floats2half2_rn(a[4], a[5]);
    h[3] = __floats2half2_rn(a[6], a[7]);
    uint4 pk = *(uint4*)h;
    __half* ar = g_Ah + (size_t)w * D + lane * 8;
    asm volatile("st.global.cs.v4.b32 [%0], {%1, %2, %3, %4};"
                 :: "l"(ar), "r"(pk.x), "r"(pk.y), "r"(pk.z), "r"(pk.w)
                 : "memory");
}

// ---------------- W prep: 2xfp16 split into fragment-major layout -----------
// Element (k,n): c=k>>6, ks=(k&63)>>4, kr=k&15; word=kr>>3, tg=(kr&7)>>1,
// halfpos=kr&1; nt=n>>3, g=n&7; lane=(g*4+tg)^ks.
__global__ void wprep_kernel(const float* __restrict__ W) {
    int idx = blockIdx.x * blockDim.x + threadIdx.x;   // 0..65535 = k*256+n
    int k = idx >> 8;
    int n = idx & 255;
    float w  = W[idx];
    __half hi = __float2half_rn(w);
    __half lo = __float2half_rn(w - __half2float(hi));
    int c = k >> 6, kk = k & 63, ks = kk >> 4, kr = kk & 15;
    int word = kr >> 3, tg = (kr & 7) >> 1, halfpos = kr & 1;
    int nt = n >> 3, g = n & 7;
    int lane = (g * 4 + tg) ^ ks;
    size_t base = ((((size_t)c * 32 + nt) * 4 + ks) * 32 + lane) * 8;
    g_FragBh[base + word * 2 + halfpos]       = hi;   // words 0,1 = bh0,bh1
    g_FragBh[base + (word + 2) * 2 + halfpos] = lo;   // words 2,3 = bl0,bl1
}

// ---------------- GEMM: out = A @ W via mma.sync f16 (2xFP16 W split) -------
// CTA 128x128, 8 warps 4x2, warp tile 32x64, BK=64, 4 K-chunks.
// A fragment-major SMEM (single buffer), B cp.async double-buffered.
#define SM_AF_F 0                        // A frags: 4096 floats (16 KB)
#define SM_B0_F 4096
#define SM_B1_F 12288
#define SMEM_FLOATS (4096 + 16384)       // 20480 floats = 80 KB

#define CP_ASYNC16(smem_u32, gptr) \
    asm volatile("cp.async.ca.shared.global [%0], [%1], 16;" \
                 :: "r"(smem_u32), "l"(gptr) : "memory")
#define CP_COMMIT() asm volatile("cp.async.commit_group;" ::: "memory")
#define CP_WAIT0()  asm volatile("cp.async.wait_group 0;" ::: "memory")
#define CP_WAIT1()  asm volatile("cp.async.wait_group 1;" ::: "memory")

__device__ __forceinline__ void mma_f16(float* c, uint4 a, uint32_t b0, uint32_t b1) {
    asm volatile(
        "mma.sync.aligned.m16n8k16.row.col.f32.f16.f16.f32 "
        "{%0,%1,%2,%3}, {%4,%5,%6,%7}, {%8,%9}, {%0,%1,%2,%3};"
        : "+f"(c[0]), "+f"(c[1]), "+f"(c[2]), "+f"(c[3])
        : "r"(a.x), "r"(a.y), "r"(a.z), "r"(a.w), "r"(b0), "r"(b1));
}

__global__ __launch_bounds__(256) void gemm_mma_kernel(float* __restrict__ out) {
    extern __shared__ float smem[];
    uint32_t* AF32 = (uint32_t*)(smem + SM_AF_F);
    uint4*    AF4  = (uint4*)(smem + SM_AF_F);

    const int tid  = threadIdx.x;
    const int wid  = tid >> 5;
    const int lane = tid & 31;
    const int g    = lane >> 2;
    const int tg   = lane & 3;
    const int wm   = wid >> 1;       // 0..3
    const int wn   = wid & 1;        // 0..1

    const size_t rowBase = (size_t)blockIdx.y * 128;
    const int    bx      = blockIdx.x;            // N tile 0..1
    const int    colBase = bx * 128;
    const __half* Atile = g_Ah + rowBase * D;

    // per-thread A load coords: 4 uint4 (8 halves each) per chunk
    const int ar  = tid >> 3;             // row 0..31 (+32*i)
    const int c8  = tid & 7;              // col-block of 8 halves within BK=64

    float acc[2][8][4];
    #pragma unroll
    for (int i = 0; i < 2; i++)
        #pragma unroll
        for (int j = 0; j < 8; j++)
            #pragma unroll
            for (int k = 0; k < 4; k++) acc[i][j][k] = 0.f;

    // ---- B cp.async: 2048 uint4 per chunk (16 nt x 4 ks x 32 lanes) ----
    uint32_t sB[2];
    sB[0] = (uint32_t)__cvta_generic_to_shared(smem + SM_B0_F);
    sB[1] = (uint32_t)__cvta_generic_to_shared(smem + SM_B1_F);
    const uint4* FB = (const uint4*)g_FragBh;

    auto cpB = [&](int c, int buf) {
        const uint4* src = FB + ((size_t)(c * 32 + bx * 16)) * 128 + tid;
        uint32_t dst = sB[buf] + tid * 16;
        #pragma unroll
        for (int i = 0; i < 8; i++)
            CP_ASYNC16(dst + i * 4096, (const void*)(src + i * 256));
    };

    uint4 pa[4];
    auto loadA = [&](int c) {
        #pragma unroll
        for (int i = 0; i < 4; i++)
            pa[i] = *(const uint4*)(Atile + (size_t)(ar + i * 32) * D + c * 64 + c8 * 8);
    };

    // prologue
    cpB(0, 0); CP_COMMIT();
    loadA(0);

    #pragma unroll 1
    for (int c = 0; c < 4; c++) {
        // ---- permute A chunk into fragment-major SMEM (no conversion) ----
        {
            const int ks    = c8 >> 1;
            const int hilo8 = c8 & 1;      // 0: a0/a1 cols, 1: a2/a3 cols
            #pragma unroll
            for (int i = 0; i < 4; i++) {
                int r  = ar + i * 32;
                int m  = r >> 4;
                int r8 = (r >> 3) & 1;
                int gg = r & 7;
                int reg = hilo8 * 2 + r8;
                int base = (m * 4 + ks) * 32;
                const uint32_t* wds = (const uint32_t*)&pa[i];
                #pragma unroll
                for (int wd = 0; wd < 4; wd++) {
                    int L = (gg * 4 + wd) ^ ks;
                    AF32[(base + L) * 4 + reg] = wds[wd];
                }
            }
        }
        // ---- prefetch next chunk ----
        if (c < 3) {
            cpB(c + 1, (c + 1) & 1); CP_COMMIT();
            loadA(c + 1);
            CP_WAIT1();
        } else {
            CP_WAIT0();
        }
        __syncthreads();

        // ---- MMA loop on chunk c ----
        const uint4* BF4 = (const uint4*)(smem + (((c & 1) == 0) ? SM_B0_F : SM_B1_F));
        #pragma unroll
        for (int ks = 0; ks < 4; ks++) {
            const int Ls = lane ^ ks;
            uint4 af[2];
            #pragma unroll
            for (int mt = 0; mt < 2; mt++)
                af[mt] = AF4[((wm * 2 + mt) * 4 + ks) * 32 + Ls];
            #pragma unroll
            for (int nt = 0; nt < 8; nt++) {
                uint4 b = BF4[((wn * 8 + nt) * 4 + ks) * 32 + Ls];
                #pragma unroll
                for (int mt = 0; mt < 2; mt++) {
                    mma_f16(acc[mt][nt], af[mt], b.x, b.y);   // A * W_hi
                    mma_f16(acc[mt][nt], af[mt], b.z, b.w);   // A * W_lo
                }
            }
        }
        __syncthreads();
    }

    // ---- epilogue ----
    #pragma unroll
    for (int mt = 0; mt < 2; mt++) {
        size_t r0 = rowBase + wm * 32 + mt * 16 + g;
        #pragma unroll
        for (int nt = 0; nt < 8; nt++) {
            int col = colBase + wn * 64 + nt * 8 + tg * 2;
            if (r0 < N_NODES)
                *(float2*)(out + r0 * D + col) = make_float2(acc[mt][nt][0], acc[mt][nt][1]);
            if (r0 + 8 < N_NODES)
                *(float2*)(out + (r0 + 8) * D + col) = make_float2(acc[mt][nt][2], acc[mt][nt][3]);
        }
    }
}

// ---------------- launch ----------------------------------------------------
extern "C" void kernel_launch(void* const* d_in, const int* in_sizes, int n_in,
                              void* d_out, int out_size) {
    const float* X  = (const float*)d_in[0];
    const void*  EI = d_in[1];
    const float* W  = (const float*)d_in[2];
    float*       out = (float*)d_out;

    cudaFuncSetAttribute(gemm_mma_kernel,
                         cudaFuncAttributeMaxDynamicSharedMemorySize,
                         SMEM_FLOATS * 4);

    detect_kernel<<<1, 256>>>((const unsigned int*)EI);
    zero_cnt_kernel<<<(N_NODES + 255) / 256, 256>>>();
    count_kernel<<<4096, 256>>>(EI);
    rdeg_kernel<<<(N_NODES + 255) / 256, 256>>>();
    xprep_kernel<<<(N_NODES * (D / 8) + 255) / 256, 256>>>(X);
    scan1_kernel<<<(N_NODES + 1023) / 1024, 256>>>();
    scan2_kernel<<<1, 128>>>();
    scan3_kernel<<<(N_NODES + 255) / 256, 256>>>();
    scatter_kernel<<<4096, 256>>>(EI);
    agg_kernel<<<(N_NODES + 7) / 8, 256>>>();
    wprep_kernel<<<256, 256>>>(W);
    gemm_mma_kernel<<<dim3(2, M_TILES), 256, SMEM_FLOATS * 4>>>(out);
}